// round 11
// baseline (speedup 1.0000x reference)
#include <cuda_runtime.h>
#include <cuda_fp16.h>

// PointWarping2 — Nadaraya-Watson Gaussian regression, fp16x2 inner loop.
// R10 inner loop (9 fma-class ops per 2-source x 1-query, validated) +
// occupancy push: MSPLIT=32 (TILE=256) -> 2048 blocks, ~10 resident/SM via
// __launch_bounds__(128,10). Split-K + fused last-block reduction.
//
//   arg  = qx*ax + qy*ay + qz*az + (aw + cn)      [half2, 2 sources packed]
//   w    = ex2.approx.f16x2(arg)
//   accum in half2, promoted to f32 every KCH pairs.
// Per-query bias cn rounds identically for all sources -> cancels in num/den.

#define Bx 2
#define N1x 8192
#define N2x 8192
#define NQ (Bx * N2x)           // 16384 queries
#define MSPLIT 32
#define TILE 256                 // sources per split
#define PAIRS (TILE / 2)         // 128 packed source-pairs per tile
#define BLK 128
#define QPT 2                    // queries per thread
#define QPB (BLK * QPT)          // 256 queries per block
#define GRIDX (NQ / QPB)         // 64 query columns
#define KCH 32                   // pairs per fp16 accumulation chunk

__device__ float4 g_partial[MSPLIT * NQ];
__device__ unsigned g_count[GRIDX];   // zero-init at load; mod trick, never reset

__device__ __forceinline__ half2 h2ex2(half2 x) {
    unsigned xu = *reinterpret_cast<unsigned*>(&x);
    unsigned yu;
    asm("ex2.approx.f16x2 %0, %1;" : "=r"(yu) : "r"(xu));
    half2 y;
    *reinterpret_cast<unsigned*>(&y) = yu;
    return y;
}
__device__ __forceinline__ half2 u2h2(unsigned u) {
    half2 h;
    *reinterpret_cast<unsigned*>(&h) = u;
    return h;
}
__device__ __forceinline__ unsigned h22u(half2 h) {
    return *reinterpret_cast<unsigned*>(&h);
}

// resol_factor may arrive as int32 or float32 bits; disambiguate.
__device__ __forceinline__ float read_scale(const void* p) {
    int iv = *(const int*)p;
    float f;
    if (iv > 0 && iv < 100000) f = (float)iv;
    else f = __int_as_float(iv);
    return 1.0f * f;  // INITIAL_RADIUS = 1.0
}

__global__ __launch_bounds__(BLK, 10) void main_kernel(
    const float* __restrict__ xyz1, const float* __restrict__ xyz2,
    const float* __restrict__ flow1, const void* __restrict__ resol,
    float* __restrict__ out) {
    __shared__ uint4 sA[PAIRS];   // (ax01, ay01, az01, aw01) half2 each
    __shared__ uint4 sF[PAIRS];   // (fx01, fy01, fz01, 0)    half2 each
    __shared__ unsigned s_old;

    int qbase = blockIdx.x * QPB;          // block stays within one batch
    int b = qbase >> 13;

    float scale = read_scale(resol);
    float L = 1.4426950408889634f / (scale * scale);
    float t2 = 2.0f * L;

    // ---- fused prep: build fp16-packed source tile (math in f32) ----
    const float* x1b = xyz1 + b * 3 * N1x;
    const float* f1b = flow1 + b * 3 * N1x;
    int m0 = blockIdx.y * TILE;
    #pragma unroll
    for (int i = threadIdx.x; i < PAIRS; i += BLK) {
        int m = m0 + 2 * i;
        float2 xx = *(const float2*)(x1b + m);
        float2 xy = *(const float2*)(x1b + N1x + m);
        float2 xz = *(const float2*)(x1b + 2 * N1x + m);
        float2 fx = *(const float2*)(f1b + m);
        float2 fy = *(const float2*)(f1b + N1x + m);
        float2 fz = *(const float2*)(f1b + 2 * N1x + m);
        float yx0 = xx.x + fx.x, yx1 = xx.y + fx.y;
        float yy0 = xy.x + fy.x, yy1 = xy.y + fy.y;
        float yz0 = xz.x + fz.x, yz1 = xz.y + fz.y;
        float aw0 = -L * (yx0 * yx0 + yy0 * yy0 + yz0 * yz0);
        float aw1 = -L * (yx1 * yx1 + yy1 * yy1 + yz1 * yz1);
        sA[i] = make_uint4(
            h22u(__floats2half2_rn(t2 * yx0, t2 * yx1)),
            h22u(__floats2half2_rn(t2 * yy0, t2 * yy1)),
            h22u(__floats2half2_rn(t2 * yz0, t2 * yz1)),
            h22u(__floats2half2_rn(aw0, aw1)));
        sF[i] = make_uint4(
            h22u(__floats2half2_rn(fx.x, fx.y)),
            h22u(__floats2half2_rn(fy.x, fy.y)),
            h22u(__floats2half2_rn(fz.x, fz.y)), 0u);
    }

    // ---- query registers (QPT queries per thread, fp16 broadcast pairs) ----
    const float* x2b = xyz2 + b * 3 * N2x;
    half2 qxh[QPT], qyh[QPT], qzh[QPT], cnh[QPT];
    #pragma unroll
    for (int k = 0; k < QPT; k++) {
        int n = (qbase + threadIdx.x + k * BLK) & (N2x - 1);
        float qx = x2b[n], qy = x2b[N2x + n], qz = x2b[2 * N2x + n];
        float cn = -L * (qx * qx + qy * qy + qz * qz);
        qxh[k] = __float2half2_rn(qx);
        qyh[k] = __float2half2_rn(qy);
        qzh[k] = __float2half2_rn(qz);
        cnh[k] = __float2half2_rn(cn);
    }

    __syncthreads();

    float accx[QPT], accy[QPT], accz[QPT], accd[QPT];
    #pragma unroll
    for (int k = 0; k < QPT; k++) accx[k] = accy[k] = accz[k] = accd[k] = 0.f;

    for (int c0 = 0; c0 < PAIRS; c0 += KCH) {
        half2 hx[QPT], hy[QPT], hz[QPT], hd[QPT];
        half2 hzero = __float2half2_rn(0.f);
        #pragma unroll
        for (int k = 0; k < QPT; k++) { hx[k] = hy[k] = hz[k] = hd[k] = hzero; }

        #pragma unroll 8
        for (int j = c0; j < c0 + KCH; j++) {
            uint4 a = sA[j];
            uint4 f = sF[j];
            half2 ax = u2h2(a.x), ay = u2h2(a.y), az = u2h2(a.z), aw = u2h2(a.w);
            half2 fx = u2h2(f.x), fy = u2h2(f.y), fz = u2h2(f.z);
            #pragma unroll
            for (int k = 0; k < QPT; k++) {
                half2 t = __hadd2(aw, cnh[k]);
                t = __hfma2(qzh[k], az, t);
                t = __hfma2(qyh[k], ay, t);
                t = __hfma2(qxh[k], ax, t);
                half2 w = h2ex2(t);
                hx[k] = __hfma2(w, fx, hx[k]);
                hy[k] = __hfma2(w, fy, hy[k]);
                hz[k] = __hfma2(w, fz, hz[k]);
                hd[k] = __hadd2(hd[k], w);
            }
        }
        // promote chunk subtotals to f32
        #pragma unroll
        for (int k = 0; k < QPT; k++) {
            float2 v;
            v = __half22float2(hx[k]); accx[k] += v.x + v.y;
            v = __half22float2(hy[k]); accy[k] += v.x + v.y;
            v = __half22float2(hz[k]); accz[k] += v.x + v.y;
            v = __half22float2(hd[k]); accd[k] += v.x + v.y;
        }
    }

    #pragma unroll
    for (int k = 0; k < QPT; k++) {
        int q = qbase + threadIdx.x + k * BLK;
        g_partial[blockIdx.y * NQ + q] =
            make_float4(accx[k], accy[k], accz[k], accd[k]);
    }

    // ---- last-block reduction for this query column ----
    __threadfence();
    if (threadIdx.x == 0)
        s_old = atomicAdd(&g_count[blockIdx.x], 1u);
    __syncthreads();
    if ((s_old % MSPLIT) != (MSPLIT - 1)) return;

    // Last of the MSPLIT splits for query column blockIdx.x:
    // register-thrifty chunked reduction, 8 loads in flight.
    const float* x2o = xyz2 + b * 3 * N2x;
    float* ob = out + b * 3 * N2x;
    #pragma unroll
    for (int k = 0; k < QPT; k++) {
        int q = qbase + threadIdx.x + k * BLK;
        float rx = 0.f, ry = 0.f, rz = 0.f, rw = 0.f;
        #pragma unroll
        for (int c = 0; c < MSPLIT / 8; c++) {
            float4 t[8];
            #pragma unroll
            for (int s = 0; s < 8; s++) t[s] = g_partial[(c * 8 + s) * NQ + q];
            #pragma unroll
            for (int s = 0; s < 8; s++) {
                rx += t[s].x; ry += t[s].y; rz += t[s].z; rw += t[s].w;
            }
        }
        int n = q & (N2x - 1);
        float inv = 1.0f / rw;
        ob[0 * N2x + n] = x2o[0 * N2x + n] - rx * inv;
        ob[1 * N2x + n] = x2o[1 * N2x + n] - ry * inv;
        ob[2 * N2x + n] = x2o[2 * N2x + n] - rz * inv;
    }
}

extern "C" void kernel_launch(void* const* d_in, const int* in_sizes, int n_in,
                              void* d_out, int out_size) {
    const float* xyz1  = (const float*)d_in[0];
    const float* xyz2  = (const float*)d_in[1];
    const float* flow1 = (const float*)d_in[2];
    const void*  resol = d_in[3];
    float* out = (float*)d_out;

    dim3 grid(GRIDX, MSPLIT);   // 64 x 32 = 2048 blocks
    main_kernel<<<grid, BLK>>>(xyz1, xyz2, flow1, resol, out);
}

// round 12
// speedup vs baseline: 1.6026x; 1.6026x over previous
#include <cuda_runtime.h>
#include <cuda_fp16.h>

// PointWarping2 — Nadaraya-Watson Gaussian regression via tensor cores.
// Attention-style: S = Q~ . A~^T (mma.m16n8k8, biases folded into padded K),
// P = ex2(S) on f16 D-fragments (D-frag == next A-frag layout, stays in regs),
// (num|den) += P . G (mma, f32 accumulate). Split-K + fused last-block reduce.
//
//   Q~ = (qx, qy, qz, 1, cn, 0, 0, 0),  cn = -L|q|^2
//   A~ = (2Lyx, 2Lyy, 2Lyz, aw, 1, 0, 0, 0),  aw = -L|y|^2,  L = log2e/s^2
//   G  = columns (fx, fy, fz, 1, 0, 0, 0, 0) per source
//   out = x2 - num/den   (w = 2^S exactly the Gaussian weight)

#define Bx 2
#define N1x 8192
#define N2x 8192
#define NQ (Bx * N2x)          // 16384 queries
#define MSPLIT 8
#define TILE (N1x / MSPLIT)     // 1024 sources per split
#define BLK 128
#define QT 2                    // 16-row mma tiles per warp
#define QPW (16 * QT)           // 32 queries per warp
#define QPB (QPW * 4)           // 128 queries per block
#define GRIDX (NQ / QPB)        // 128 query columns
#define FSTRIDE (TILE + 8)      // f16 elems; staggers Fc rows across banks

__device__ float4 g_partial[MSPLIT * NQ];
__device__ unsigned g_count[GRIDX];   // zero-init at load; mod trick, never reset

__device__ __forceinline__ unsigned h2ex2u(unsigned xu) {
    unsigned yu;
    asm("ex2.approx.f16x2 %0, %1;" : "=r"(yu) : "r"(xu));
    return yu;
}
__device__ __forceinline__ unsigned h22u(half2 h) {
    return *reinterpret_cast<unsigned*>(&h);
}
__device__ __forceinline__ void mma_s(unsigned& d0, unsigned& d1,
                                      unsigned a0, unsigned a1, unsigned b0) {
    unsigned z = 0u;
    asm("mma.sync.aligned.m16n8k8.row.col.f16.f16.f16.f16 "
        "{%0,%1}, {%2,%3}, {%4}, {%5,%6};"
        : "=r"(d0), "=r"(d1)
        : "r"(a0), "r"(a1), "r"(b0), "r"(z), "r"(z));
}
__device__ __forceinline__ void mma_acc(float& c0, float& c1, float& c2, float& c3,
                                        unsigned p0, unsigned p1, unsigned b0) {
    asm("mma.sync.aligned.m16n8k8.row.col.f32.f16.f16.f32 "
        "{%0,%1,%2,%3}, {%4,%5}, {%6}, {%0,%1,%2,%3};"
        : "+f"(c0), "+f"(c1), "+f"(c2), "+f"(c3)
        : "r"(p0), "r"(p1), "r"(b0));
}

// resol_factor may arrive as int32 or float32 bits; disambiguate.
__device__ __forceinline__ float read_scale(const void* p) {
    int iv = *(const int*)p;
    float f;
    if (iv > 0 && iv < 100000) f = (float)iv;
    else f = __int_as_float(iv);
    return 1.0f * f;  // INITIAL_RADIUS = 1.0
}

__global__ __launch_bounds__(BLK) void main_kernel(
    const float* __restrict__ xyz1, const float* __restrict__ xyz2,
    const float* __restrict__ flow1, const void* __restrict__ resol,
    float* __restrict__ out) {
    __shared__ uint2 sA[TILE];          // (h2(ax,ay), h2(az,aw)) per source
    __shared__ half  sFc[3 * FSTRIDE];  // component-major flow (fx|fy|fz rows)
    __shared__ unsigned s_old;

    int tid = threadIdx.x;
    int warp = tid >> 5;
    int lane = tid & 31;
    int gid = lane >> 2;     // groupID  (row / B-col selector)
    int tig = lane & 3;      // thread-in-group (K-pair selector)

    int qbase = blockIdx.x * QPB;       // block stays within one batch
    int b = qbase >> 13;

    float scale = read_scale(resol);
    float L = 1.4426950408889634f / (scale * scale);
    float t2 = 2.0f * L;

    // ---- fused prep: packed source tile ----
    const float* x1b = xyz1 + b * 3 * N1x;
    const float* f1b = flow1 + b * 3 * N1x;
    int m0 = blockIdx.y * TILE;
    #pragma unroll
    for (int i = tid; i < TILE; i += BLK) {
        int m = m0 + i;
        float fx = f1b[m], fy = f1b[N1x + m], fz = f1b[2 * N1x + m];
        float yx = x1b[m] + fx;
        float yy = x1b[N1x + m] + fy;
        float yz = x1b[2 * N1x + m] + fz;
        float aw = -L * (yx * yx + yy * yy + yz * yz);
        sA[i] = make_uint2(h22u(__floats2half2_rn(t2 * yx, t2 * yy)),
                           h22u(__floats2half2_rn(t2 * yz, aw)));
        sFc[i]               = __float2half(fx);
        sFc[FSTRIDE + i]     = __float2half(fy);
        sFc[2 * FSTRIDE + i] = __float2half(fz);
    }

    // ---- Q fragments: A-operand of mma1, per q-tile ----
    // Q~ row layout over K=8: (qx,qy | qz,1 | cn,0 | 0,0) keyed by tig.
    const float* x2b = xyz2 + b * 3 * N2x;
    int qtb = qbase + warp * QPW;
    unsigned qa0[QT], qa1[QT];
    #pragma unroll
    for (int t = 0; t < QT; t++) {
        #pragma unroll
        for (int rr = 0; rr < 2; rr++) {
            int q = qtb + t * 16 + gid + rr * 8;
            int n = q & (N2x - 1);
            float qx = x2b[n], qy = x2b[N2x + n], qz = x2b[2 * N2x + n];
            float cn = -L * (qx * qx + qy * qy + qz * qz);
            float e0, e1;
            if      (tig == 0) { e0 = qx; e1 = qy;  }
            else if (tig == 1) { e0 = qz; e1 = 1.f; }
            else if (tig == 2) { e0 = cn; e1 = 0.f; }
            else               { e0 = 0.f; e1 = 0.f; }
            unsigned v = h22u(__floats2half2_rn(e0, e1));
            if (rr == 0) qa0[t] = v; else qa1[t] = v;
        }
    }

    __syncthreads();

    // constants for the B fragments' padded lanes
    unsigned cB1 = (tig == 2) ? 0x00003C00u : 0u;   // (1.0, 0) at K=4,5
    unsigned cB2 = (gid == 3) ? 0x3C003C00u : 0u;   // G col 3 = ones
    const unsigned* aU = (const unsigned*)sA;       // [TILE*2]
    const half* fBase = sFc + gid * FSTRIDE;        // valid for gid<3

    float acc[QT][4];
    #pragma unroll
    for (int t = 0; t < QT; t++)
        acc[t][0] = acc[t][1] = acc[t][2] = acc[t][3] = 0.f;

    #pragma unroll 4
    for (int sb = 0; sb < TILE; sb += 8) {
        // mma1 B: A~^T tile — col = source (gid), K-pair selected by tig
        unsigned b1 = cB1;
        if (tig < 2) b1 = aU[2 * (sb + gid) + tig];
        // mma2 B: G tile — col = component (gid), rows = sources 2tig,2tig+1
        unsigned b2 = cB2;
        if (gid < 3) b2 = *(const unsigned*)(fBase + sb + 2 * tig);

        #pragma unroll
        for (int t = 0; t < QT; t++) {
            unsigned s0, s1;
            mma_s(s0, s1, qa0[t], qa1[t], b1);     // S = Q~ . A~^T  (f16)
            unsigned p0 = h2ex2u(s0);               // P = 2^S
            unsigned p1 = h2ex2u(s1);
            mma_acc(acc[t][0], acc[t][1], acc[t][2], acc[t][3], p0, p1, b2);
        }
    }

    // ---- store partials: tig 0 holds (numx,numy), tig 1 holds (numz,den) ----
    if (tig < 2) {
        #pragma unroll
        for (int t = 0; t < QT; t++) {
            int q1 = qtb + t * 16 + gid;
            int q2 = q1 + 8;
            float2* p1 = (float2*)&g_partial[blockIdx.y * NQ + q1];
            float2* p2 = (float2*)&g_partial[blockIdx.y * NQ + q2];
            p1[tig] = make_float2(acc[t][0], acc[t][1]);
            p2[tig] = make_float2(acc[t][2], acc[t][3]);
        }
    }

    // ---- last-block reduction for this query column ----
    __threadfence();
    if (tid == 0)
        s_old = atomicAdd(&g_count[blockIdx.x], 1u);
    __syncthreads();
    if ((s_old % MSPLIT) != (MSPLIT - 1)) return;

    {
        int q = qbase + tid;                 // 128 threads, 128 queries
        float rx = 0.f, ry = 0.f, rz = 0.f, rw = 0.f;
        float4 v[MSPLIT];
        #pragma unroll
        for (int s = 0; s < MSPLIT; s++) v[s] = g_partial[s * NQ + q];
        #pragma unroll
        for (int s = 0; s < MSPLIT; s++) {
            rx += v[s].x; ry += v[s].y; rz += v[s].z; rw += v[s].w;
        }
        int n = q & (N2x - 1);
        float inv = 1.0f / rw;
        const float* x2o = xyz2 + b * 3 * N2x;
        float* ob = out + b * 3 * N2x;
        ob[0 * N2x + n] = x2o[0 * N2x + n] - rx * inv;
        ob[1 * N2x + n] = x2o[1 * N2x + n] - ry * inv;
        ob[2 * N2x + n] = x2o[2 * N2x + n] - rz * inv;
    }
}

extern "C" void kernel_launch(void* const* d_in, const int* in_sizes, int n_in,
                              void* d_out, int out_size) {
    const float* xyz1  = (const float*)d_in[0];
    const float* xyz2  = (const float*)d_in[1];
    const float* flow1 = (const float*)d_in[2];
    const void*  resol = d_in[3];
    float* out = (float*)d_out;

    dim3 grid(GRIDX, MSPLIT);   // 128 x 8 = 1024 blocks
    main_kernel<<<grid, BLK>>>(xyz1, xyz2, flow1, resol, out);
}